// round 3
// baseline (speedup 1.0000x reference)
#include <cuda_runtime.h>
#include <math.h>

// Problem constants
#define NN0 4096
#define NN1 1024
#define FIN 8
#define HH 64
#define FF 67
#define FPAD 68
#define LLAT 32

// Scratch (device globals: no allocation allowed)
__device__ float    g_xf0[NN0 * FPAD];   // encoder out || pos  (conv0 input features)
__device__ float    g_out0[NN0 * HH];    // conv0 accumulation
__device__ float    g_h0s[NN0 * HH];     // sin(0.01*conv0)
__device__ unsigned g_maxkey[NN0 * HH];  // monotone-key max pool
__device__ float    g_xf1[NN1 * FPAD];   // pooled feats || pool_pos1
__device__ float    g_out1[NN1 * HH];    // conv1 accumulation

__device__ __forceinline__ unsigned fkey(float f) {
    int i = __float_as_int(f);
    return (i < 0) ? ~(unsigned)i : ((unsigned)i | 0x80000000u);
}
__device__ __forceinline__ float funkey(unsigned u) {
    int i = (u & 0x80000000u) ? (int)(u & 0x7fffffffu) : ~(int)u;
    return __int_as_float(i);
}

// ---- packed f32x2 helpers (FFMA2 path: 2 FMAs per lane per instruction) ----
__device__ __forceinline__ unsigned long long pk2(float lo, float hi) {
    unsigned long long r;
    asm("mov.b64 %0, {%1, %2};" : "=l"(r) : "f"(lo), "f"(hi));
    return r;
}
__device__ __forceinline__ void upk2(unsigned long long v, float& lo, float& hi) {
    asm("mov.b64 {%0, %1}, %2;" : "=f"(lo), "=f"(hi) : "l"(v));
}
__device__ __forceinline__ unsigned long long fma2(unsigned long long a,
                                                   unsigned long long b,
                                                   unsigned long long c) {
    unsigned long long d;
    asm("fma.rn.f32x2 %0, %1, %2, %3;" : "=l"(d) : "l"(a), "l"(b), "l"(c));
    return d;
}

// ---------------- encode: g_xf0 = [sin(0.01*(x@W+b)) || pos], init out0 with bias
__global__ void k_encode(const float* __restrict__ x, const float* __restrict__ pos,
                         const float* __restrict__ w, const float* __restrict__ b,
                         const float* __restrict__ bias0) {
    int n = blockIdx.x, t = threadIdx.x;  // block = 64
    float acc = b[t];
#pragma unroll
    for (int f = 0; f < FIN; f++) acc = fmaf(x[n * FIN + f], w[f * HH + t], acc);
    g_xf0[n * FPAD + t] = sinf(0.01f * acc);
    if (t < 3)  g_xf0[n * FPAD + 64 + t] = pos[n * 3 + t];
    if (t == 3) g_xf0[n * FPAD + 67] = 0.f;
    g_out0[n * HH + t] = bias0[t];
}

// ---------------- the kernel-conv: warp per edge, channels packed in f32x2 ----
// dynamic smem layout (bytes):
#define SM_WDUP   0          // ull[64*64]    (w1 duplicated pairs)   32768
#define SM_W2P    32768      // ull[67*32]    (paired w2)             17152
#define SM_TSD    49920      // ull[8][64]    (t duplicated)           4096
#define SM_XJS    54016      // ull[8][68]    (x_j duplicated)         4352
#define SM_B1D    58368      // ull[64]                                 512
#define SM_B2D    58880      // ull[68]                                 544
#define SM_BAS    59424      // float[8][64]                           2048
#define SM_W0S    61472      // float[192]                              768
#define SM_DWS    62240      // float[64]                               256
#define SM_D32    62496      // float[64]                               256
#define SM_B0S    62752      // float[64]                               256
#define SM_TOTAL  63008

__global__ __launch_bounds__(256, 1)
void k_conv(const float* __restrict__ xf, const int* __restrict__ ei,
            int Eorig, int Etot, const float* __restrict__ pos,
            const float* __restrict__ w0, const float* __restrict__ b0,
            const float* __restrict__ w1, const float* __restrict__ b1,
            const float* __restrict__ w2, const float* __restrict__ b2,
            float* __restrict__ out) {
    extern __shared__ __align__(16) char smem[];
    unsigned long long* wdup = (unsigned long long*)(smem + SM_WDUP);
    ulonglong2*         wd2  = (ulonglong2*)(smem + SM_WDUP);
    unsigned long long* w2p  = (unsigned long long*)(smem + SM_W2P);
    unsigned long long* tsd  = (unsigned long long*)(smem + SM_TSD);
    unsigned long long* xjs  = (unsigned long long*)(smem + SM_XJS);
    unsigned long long* b1d  = (unsigned long long*)(smem + SM_B1D);
    unsigned long long* b2d  = (unsigned long long*)(smem + SM_B2D);
    float*              bas  = (float*)(smem + SM_BAS);
    float*              w0s  = (float*)(smem + SM_W0S);
    float*              dws  = (float*)(smem + SM_DWS);
    float*              d32s = (float*)(smem + SM_D32);
    float*              b0s  = (float*)(smem + SM_B0S);

    int tid = threadIdx.x;
    // duplicated w1 pairs: wdup[h*64+k] = (w1[h,k], w1[h,k])
    for (int i = tid; i < HH * HH; i += 256) {
        float v = w1[i];
        wdup[i] = pk2(v, v);
    }
    // paired w2: w2p[f*32+i] = (w2[i,f], w2[i+32,f])
    for (int i = tid; i < FF * 32; i += 256) {
        int f = i >> 5, h = i & 31;
        w2p[i] = pk2(w2[h * FF + f], w2[(h + 32) * FF + f]);
    }
    if (tid < 192) w0s[tid] = 0.1f * w0[tid];
    else {
        float d = 0.1f * w0[tid];        // row 3 (tid in [192,256))
        dws[tid - 192]  = d;
        d32s[tid - 192] = 32.f * d;
    }
    if (tid < HH) {
        b0s[tid] = 0.1f * b0[tid];
        b1d[tid] = pk2(b1[tid], b1[tid]);
    }
    if (tid < FPAD) {
        float v = (tid < FF) ? b2[tid] : 0.f;
        b2d[tid] = pk2(v, v);
    }
    __syncthreads();

    int w = tid >> 5, lane = tid & 31;
    int e = blockIdx.x * 8 + w;
    if (e >= Etot) return;

    int src, dst;
    if (e < Eorig) { src = ei[e]; dst = ei[Eorig + e]; }
    else           { src = dst = e - Eorig; }

    float rx = pos[dst * 3 + 0] - pos[src * 3 + 0];
    float ry = pos[dst * 3 + 1] - pos[src * 3 + 1];
    float rz = pos[dst * 3 + 2] - pos[src * 3 + 2];
    float f0 = 0.f, f1 = 0.f, f2 = 0.f;
    if (!(rx == 0.f && ry == 0.f && rz == 0.f)) {
        float rho = sqrtf(rx * rx + ry * ry + rz * rz);
        const float INV_PI = 0.31830988618379067f;
        f0 = rho;
        f1 = atan2f(ry, rx) * INV_PI;
        f2 = asinf(fminf(fmaxf(rz / rho, -1.f), 1.f)) * INV_PI;
    }

    // gather x_j duplicated (pad col 67 == 0 lives in xf)
    {
        float va = xf[src * FPAD + lane];
        float vb = xf[src * FPAD + lane + 32];
        xjs[w * FPAD + lane]      = pk2(va, va);
        xjs[w * FPAD + lane + 32] = pk2(vb, vb);
        if (lane < 4) {
            float vc = xf[src * FPAD + 64 + lane];
            xjs[w * FPAD + 64 + lane] = pk2(vc, vc);
        }
    }
    // bases (scaled by 0.1): lane owns h = lane, lane+32
    int ha = lane, hb = lane + 32;
    bas[w * HH + ha] = fmaf(f0, w0s[ha], fmaf(f1, w0s[64 + ha], fmaf(f2, w0s[128 + ha], b0s[ha])));
    bas[w * HH + hb] = fmaf(f0, w0s[hb], fmaf(f1, w0s[64 + hb], fmaf(f2, w0s[128 + hb], b0s[hb])));
    __syncwarp();

    // t pair: (t[h=lane], t[h=lane+32]); xb2 duplicated in both halves
    unsigned long long tp = pk2(0.f, 0.f), xb2p = pk2(0.f, 0.f);
#pragma unroll
    for (int f = 0; f < FF; f++) {
        unsigned long long xv2 = xjs[w * FPAD + f];       // broadcast
        tp   = fma2(w2p[f * 32 + lane], xv2, tp);
        xb2p = fma2(b2d[f], xv2, xb2p);
    }
    {
        float tlo, thi;
        upk2(tp, tlo, thi);
        tsd[w * HH + lane]      = pk2(tlo, tlo);
        tsd[w * HH + lane + 32] = pk2(thi, thi);
    }
    __syncwarp();

    // h0 packed: lo = channel c=lane, hi = channel c=lane+32
    float cA = (float)lane;
    unsigned long long h0p[HH];
#pragma unroll
    for (int h = 0; h < HH; h++) {
        float argA = fmaf(cA, dws[h], bas[w * HH + h]);
        float argB = argA + d32s[h];
        h0p[h] = pk2(__sinf(argA), __sinf(argB));
    }

    unsigned long long msg = xb2p;
#pragma unroll 1
    for (int kt = 0; kt < 16; kt++) {
        unsigned long long a0 = b1d[4 * kt + 0], a1 = b1d[4 * kt + 1];
        unsigned long long a2 = b1d[4 * kt + 2], a3 = b1d[4 * kt + 3];
#pragma unroll
        for (int h = 0; h < HH; h++) {
            ulonglong2 q0 = wd2[h * 32 + 2 * kt];       // (w[h,4kt], w[h,4kt+1]) dup pairs
            ulonglong2 q1 = wd2[h * 32 + 2 * kt + 1];   // (w[h,4kt+2], w[h,4kt+3])
            a0 = fma2(h0p[h], q0.x, a0);
            a1 = fma2(h0p[h], q0.y, a1);
            a2 = fma2(h0p[h], q1.x, a2);
            a3 = fma2(h0p[h], q1.y, a3);
        }
#pragma unroll
        for (int j = 0; j < 4; j++) {
            unsigned long long aj = (j == 0) ? a0 : (j == 1) ? a1 : (j == 2) ? a2 : a3;
            float lo, hi;
            upk2(aj, lo, hi);
            unsigned long long s = pk2(__sinf(0.1f * lo), __sinf(0.1f * hi));
            msg = fma2(s, tsd[w * HH + 4 * kt + j], msg);
        }
    }
    {
        float mlo, mhi;
        upk2(msg, mlo, mhi);
        atomicAdd(&out[dst * HH + lane],      mlo);
        atomicAdd(&out[dst * HH + lane + 32], mhi);
    }
}

// ---------------- post conv0: sin + init max keys (self-loop = init value)
__global__ void k_post0() {
    int i = blockIdx.x * 256 + threadIdx.x;  // NN0*HH total
    float v = sinf(0.01f * g_out0[i]);
    g_h0s[i] = v;
    g_maxkey[i] = fkey(v);
}

// ---------------- scatter-max over original edges
__global__ void k_smax(const int* __restrict__ ei, int E) {
    int idx = blockIdx.x * 256 + threadIdx.x;
    if (idx >= E * HH) return;
    int e = idx >> 6, c = idx & 63;
    int src = ei[e], dst = ei[E + e];
    atomicMax(&g_maxkey[dst * HH + c], fkey(g_h0s[src * HH + c]));
}

// ---------------- build conv1 input + init out1 with bias
__global__ void k_build1(const int* __restrict__ keep, const float* __restrict__ ppos,
                         const float* __restrict__ bias1) {
    int i = blockIdx.x, t = threadIdx.x;  // block = 64
    int n = keep[i];
    g_xf1[i * FPAD + t] = funkey(g_maxkey[n * HH + t]);
    if (t < 3)  g_xf1[i * FPAD + 64 + t] = ppos[i * 3 + t];
    if (t == 3) g_xf1[i * FPAD + 67] = 0.f;
    g_out1[i * HH + t] = bias1[t];
}

// ---------------- decode
__global__ void k_decode(const float* __restrict__ w, const float* __restrict__ b,
                         float* __restrict__ out) {
    __shared__ float hs[HH];
    int i = blockIdx.x, t = threadIdx.x;  // block = 64
    hs[t] = sinf(0.01f * g_out1[i * HH + t]);
    __syncthreads();
    if (t < LLAT) {
        float acc = b[t];
#pragma unroll
        for (int c = 0; c < HH; c++) acc = fmaf(hs[c], w[c * LLAT + t], acc);
        out[i * LLAT + t] = sinf(0.01f * acc);
    }
}

extern "C" void kernel_launch(void* const* d_in, const int* in_sizes, int n_in,
                              void* d_out, int out_size) {
    const float* x = (const float*)d_in[0];
    const float* pos;
    const int*   ei;
    int szEi;
    if (in_sizes[1] == NN0 * 3) {  // dict order: x, pos, edge_index
        pos = (const float*)d_in[1]; ei = (const int*)d_in[2]; szEi = in_sizes[2];
    } else {                       // signature order: x, edge_index, pos
        ei = (const int*)d_in[1]; pos = (const float*)d_in[2]; szEi = in_sizes[1];
    }
    const int*   ei1    = (const int*)d_in[3];
    const float* ppos   = (const float*)d_in[4];
    const int*   keep   = (const int*)d_in[5];
    const float* lin0_w = (const float*)d_in[6];
    const float* lin0_b = (const float*)d_in[7];
    const float* lin1_w = (const float*)d_in[8];
    const float* lin1_b = (const float*)d_in[9];
    const float* c0w0 = (const float*)d_in[10], *c0b0 = (const float*)d_in[11];
    const float* c0w1 = (const float*)d_in[12], *c0b1 = (const float*)d_in[13];
    const float* c0w2 = (const float*)d_in[14], *c0b2 = (const float*)d_in[15];
    const float* c0bias = (const float*)d_in[16];
    const float* c1w0 = (const float*)d_in[17], *c1b0 = (const float*)d_in[18];
    const float* c1w1 = (const float*)d_in[19], *c1b1 = (const float*)d_in[20];
    const float* c1w2 = (const float*)d_in[21], *c1b2 = (const float*)d_in[22];
    const float* c1bias = (const float*)d_in[23];

    int E0 = szEi / 2;            // 16384
    int E1 = in_sizes[3] / 2;     // 8192
    int E0t = E0 + NN0;           // + self loops
    int E1t = E1 + NN1;

    float *xf0, *out0, *xf1, *out1;
    cudaGetSymbolAddress((void**)&xf0,  g_xf0);
    cudaGetSymbolAddress((void**)&out0, g_out0);
    cudaGetSymbolAddress((void**)&xf1,  g_xf1);
    cudaGetSymbolAddress((void**)&out1, g_out1);

    cudaFuncSetAttribute(k_conv, cudaFuncAttributeMaxDynamicSharedMemorySize, SM_TOTAL);

    k_encode<<<NN0, 64>>>(x, pos, lin0_w, lin0_b, c0bias);
    k_conv<<<(E0t + 7) / 8, 256, SM_TOTAL>>>(xf0, ei, E0, E0t, pos,
                                             c0w0, c0b0, c0w1, c0b1, c0w2, c0b2, out0);
    k_post0<<<(NN0 * HH) / 256, 256>>>();
    k_smax<<<(E0 * HH + 255) / 256, 256>>>(ei, E0);
    k_build1<<<NN1, 64>>>(keep, ppos, c1bias);
    k_conv<<<(E1t + 7) / 8, 256, SM_TOTAL>>>(xf1, ei1, E1, E1t, ppos,
                                             c1w0, c1b0, c1w1, c1b1, c1w2, c1b2, out1);
    k_decode<<<NN1, 64>>>(lin1_w, lin1_b, (float*)d_out);
}

// round 11
// speedup vs baseline: 2.6459x; 2.6459x over previous
#include <cuda_runtime.h>
#include <cuda_fp16.h>
#include <math.h>
#include <stdint.h>

#define NN0 4096
#define NN1 1024
#define FIN 8
#define HH 64
#define FF 67
#define FPAD 68
#define LLAT 32
#define TM 128
#define CSPL 4          // channel splits per tile (16 channels per block)
#define MAXT 160        // max edge tiles (conv0: 20480/128)

// ---------------- device scratch (no allocation allowed) ----------------
__device__ float    g_xf0[NN0 * FPAD];
__device__ float    g_out0[NN0 * HH];
__device__ float    g_h0s[NN0 * HH];
__device__ unsigned g_maxkey[NN0 * HH];
__device__ float    g_xf1[NN1 * FPAD];
__device__ float    g_out1[NN1 * HH];
__device__ float4   g_aimg[MAXT * 2048];   // per tile: 128x128 f16 plain row-major (32KB)
__device__ float4   g_w1cs[64 * 1024];     // per c: 64x128 f16 plain row-major (16KB)
__device__ float    g_t[MAXT * 128 * 64];
__device__ float    g_xb2[MAXT * 128];
__device__ int      g_dst[MAXT * 128];

__device__ __forceinline__ unsigned fkey(float f) {
    int i = __float_as_int(f);
    return (i < 0) ? ~(unsigned)i : ((unsigned)i | 0x80000000u);
}
__device__ __forceinline__ float funkey(unsigned u) {
    int i = (u & 0x80000000u) ? (int)(u & 0x7fffffffu) : ~(int)u;
    return __int_as_float(i);
}
__device__ __forceinline__ uint32_t smem_u32(const void* p) {
    uint32_t a;
    asm("{ .reg .u64 t; cvta.to.shared.u64 t, %1; cvt.u32.u64 %0, t; }" : "=r"(a) : "l"(p));
    return a;
}

// ---------------- encode ----------------
__global__ void k_encode(const float* __restrict__ x, const float* __restrict__ pos,
                         const float* __restrict__ w, const float* __restrict__ b,
                         const float* __restrict__ bias0) {
    int n = blockIdx.x, t = threadIdx.x;  // block 64
    float acc = b[t];
#pragma unroll
    for (int f = 0; f < FIN; f++) acc = fmaf(x[n * FIN + f], w[f * HH + t], acc);
    g_xf0[n * FPAD + t] = sinf(0.01f * acc);
    if (t < 3)  g_xf0[n * FPAD + 64 + t] = pos[n * 3 + t];
    if (t == 3) g_xf0[n * FPAD + 67] = 0.f;
    g_out0[n * HH + t] = bias0[t];
}

// ---------------- prep: A image (sinα|cosα f16), t = x_j@w2^T, xb2, dst --------
__global__ __launch_bounds__(256)
void k_prep(const float* __restrict__ xf, const int* __restrict__ ei,
            int Eorig, int Etot, const float* __restrict__ pos,
            const float* __restrict__ w0, const float* __restrict__ b0,
            const float* __restrict__ w2, const float* __restrict__ b2) {
    __shared__ float w2s[HH * FF];
    __shared__ float w0s[192], b0s[HH], b2s[FF];
    __shared__ float xjs[8][FPAD];
    int tid = threadIdx.x;
    for (int i = tid; i < HH * FF; i += 256) w2s[i] = w2[i];
    if (tid < 192) w0s[tid] = 0.1f * w0[tid];
    if (tid < HH)  b0s[tid] = 0.1f * b0[tid];
    if (tid < FF)  b2s[tid] = b2[tid];
    __syncthreads();

    int w = tid >> 5, lane = tid & 31;
    int e = blockIdx.x * 8 + w;
    if (e >= Etot) return;
    int src, dst;
    if (e < Eorig) { src = ei[e]; dst = ei[Eorig + e]; }
    else           { src = dst = e - Eorig; }
    if (lane == 0) g_dst[e] = dst;

    float rx = pos[dst * 3 + 0] - pos[src * 3 + 0];
    float ry = pos[dst * 3 + 1] - pos[src * 3 + 1];
    float rz = pos[dst * 3 + 2] - pos[src * 3 + 2];
    float f0 = 0.f, f1 = 0.f, f2 = 0.f;
    if (!(rx == 0.f && ry == 0.f && rz == 0.f)) {
        float rho = sqrtf(rx * rx + ry * ry + rz * rz);
        const float INV_PI = 0.31830988618379067f;
        f0 = rho;
        f1 = atan2f(ry, rx) * INV_PI;
        f2 = asinf(fminf(fmaxf(rz / rho, -1.f), 1.f)) * INV_PI;
    }
    xjs[w][lane]      = xf[src * FPAD + lane];
    xjs[w][lane + 32] = xf[src * FPAD + lane + 32];
    if (lane < 4) xjs[w][lane + 64] = xf[src * FPAD + 64 + lane];
    __syncwarp();

    int ha = lane, hb = lane + 32;
    float t0 = 0.f, t1 = 0.f, xb2 = 0.f;
#pragma unroll
    for (int f = 0; f < FF; f++) {
        float xv = xjs[w][f];
        t0  = fmaf(w2s[ha * FF + f], xv, t0);
        t1  = fmaf(w2s[hb * FF + f], xv, t1);
        xb2 = fmaf(b2s[f], xv, xb2);
    }
    g_t[e * 64 + ha] = t0;
    g_t[e * 64 + hb] = t1;
    if (lane == 0) g_xb2[e] = xb2;

    // alpha for h = 2*lane, 2*lane+1 (pre-scaled by 0.1)
    int h0i = 2 * lane, h1i = 2 * lane + 1;
    float aA = fmaf(f0, w0s[h0i], fmaf(f1, w0s[64 + h0i], fmaf(f2, w0s[128 + h0i], b0s[h0i])));
    float aB = fmaf(f0, w0s[h1i], fmaf(f1, w0s[64 + h1i], fmaf(f2, w0s[128 + h1i], b0s[h1i])));
    // A row: cols [0,64) = sin(alpha_h), cols [64,128) = cos(alpha_h)
    __half* img = (__half*)g_aimg + (e >> 7) * 16384;
    int m = e & 127;
    *(__half2*)&img[m * 128 + 2 * lane]      = __floats2half2_rn(__sinf(aA), __sinf(aB));
    *(__half2*)&img[m * 128 + 64 + 2 * lane] = __floats2half2_rn(__cosf(aA), __cosf(aB));
}

// ---------------- per-channel B image: rows n (64), cols k (128) f16, plain ----
// B[c][n][k]: k<64 -> 0.1*cos(c*delta_h)*w1[h,n] (h=k); k>=64 -> 0.1*sin(c*delta_h)*w1[h,n]
__global__ void k_w1cs(const float* __restrict__ w0, const float* __restrict__ w1) {
    int c = blockIdx.x, n = threadIdx.x;  // block 64
    __half* img = (__half*)g_w1cs + c * 8192;
    float cf = (float)c;
#pragma unroll 8
    for (int j = 0; j < 32; j++) {
        int h0i = 2 * j, h1i = 2 * j + 1;
        float d0 = 0.1f * w0[192 + h0i], d1 = 0.1f * w0[192 + h1i];
        float w00 = w1[h0i * 64 + n],    w10 = w1[h1i * 64 + n];
        *(__half2*)&img[n * 128 + 2 * j] =
            __floats2half2_rn(0.1f * __cosf(cf * d0) * w00, 0.1f * __cosf(cf * d1) * w10);
        *(__half2*)&img[n * 128 + 64 + 2 * j] =
            __floats2half2_rn(0.1f * __sinf(cf * d0) * w00, 0.1f * __sinf(cf * d1) * w10);
    }
}

// ---------------- HMMA kernel: block = (tile, 16-channel slice), 8 warps -------
// LDA=136 halves (272B stride; 272 mod 128 = 16 -> 8 ldmatrix rows sweep all banks)
#define LDA 136
#define SMA_BYTES   (128 * LDA * 2)              // 34816
#define SMB_BYTES   (64 * LDA * 2)               // 17408
#define SMB_OFF     SMA_BYTES
#define SMBB_OFF    (SMA_BYTES + 2 * SMB_BYTES)  // 69632
#define SM_TOTAL    (SMBB_OFF + 256)

__global__ __launch_bounds__(256, 2)
void k_mma(const float4* __restrict__ aimg, const float4* __restrict__ w1cs,
           const float* __restrict__ tg, const float* __restrict__ xb2g,
           const int* __restrict__ dstg, const float* __restrict__ b1,
           float* __restrict__ out) {
    extern __shared__ __align__(16) char sm[];
    __half* smA  = (__half*)sm;
    __half* smB0 = (__half*)(sm + SMB_OFF);
    __half* smB1 = (__half*)(sm + SMB_OFF + SMB_BYTES);
    float*  bb   = (float*)(sm + SMBB_OFF);

    int tid = threadIdx.x, w = tid >> 5, lane = tid & 31;
    int tile  = blockIdx.x / CSPL;
    int cbase = (blockIdx.x % CSPL) * (64 / CSPL);

    // copy A (padded) + B for first channel
    const float4* ag = aimg + tile * 2048;
    for (int i = tid; i < 2048; i += 256) {
        int row = i >> 4, ch = i & 15;
        *(float4*)&smA[row * LDA + ch * 8] = ag[i];
    }
    {
        const float4* bg = w1cs + cbase * 1024;
        for (int i = tid; i < 1024; i += 256) {
            int row = i >> 4, ch = i & 15;
            *(float4*)&smB0[row * LDA + ch * 8] = bg[i];
        }
    }
    if (tid < 64) bb[tid] = 0.1f * b1[tid];
    __syncthreads();

    // persistent A fragments: warp w owns edge rows 16w..16w+15
    uint32_t A[8][4];
    {
        int arow = 16 * w + (lane & 15);
#pragma unroll
        for (int kt = 0; kt < 8; kt++) {
            uint32_t a = smem_u32(&smA[arow * LDA + kt * 16 + (lane >> 4) * 8]);
            asm volatile("ldmatrix.sync.aligned.m8n8.x4.shared.b16 {%0,%1,%2,%3}, [%4];"
                         : "=r"(A[kt][0]), "=r"(A[kt][1]), "=r"(A[kt][2]), "=r"(A[kt][3])
                         : "r"(a));
        }
    }

    // per-thread t values (cols fixed across channels)
    int q = lane >> 2, qi = lane & 3;
    int r1 = 16 * w + q, r2 = r1 + 8;
    int e1 = tile * 128 + r1, e2 = tile * 128 + r2;
    float t1r[16], t2r[16];
#pragma unroll
    for (int nt = 0; nt < 8; nt++) {
        int col = nt * 8 + qi * 2;
        float2 v1 = *(const float2*)&tg[e1 * 64 + col];
        float2 v2 = *(const float2*)&tg[e2 * 64 + col];
        t1r[2 * nt] = v1.x; t1r[2 * nt + 1] = v1.y;
        t2r[2 * nt] = v2.x; t2r[2 * nt + 1] = v2.y;
    }
    float xbv1 = xb2g[e1], xbv2 = xb2g[e2];
    int dA = dstg[e1], dB = dstg[e2];

    const int CH = 64 / CSPL;
    for (int cc = 0; cc < CH; cc++) {
        __half* Bcur  = (cc & 1) ? smB1 : smB0;
        __half* Bnext = (cc & 1) ? smB0 : smB1;
        // prefetch next channel's B into regs (LDG issues now, STS after compute)
        float4 pf[4];
        if (cc + 1 < CH) {
            const float4* nb = w1cs + (cbase + cc + 1) * 1024;
#pragma unroll
            for (int j = 0; j < 4; j++) pf[j] = nb[j * 256 + tid];
        }
        float pm1 = 0.f, pm2 = 0.f;
#pragma unroll
        for (int nt = 0; nt < 8; nt++) {
            float d0 = 0.f, d1f = 0.f, d2f = 0.f, d3 = 0.f;
#pragma unroll
            for (int kt = 0; kt < 8; kt++) {
                uint32_t ba = smem_u32(&Bcur[(nt * 8 + (lane & 7)) * LDA +
                                             kt * 16 + ((lane >> 3) & 1) * 8]);
                uint32_t b0, b1r;
                asm volatile("ldmatrix.sync.aligned.m8n8.x2.shared.b16 {%0,%1}, [%2];"
                             : "=r"(b0), "=r"(b1r) : "r"(ba));
                asm volatile(
                    "mma.sync.aligned.m16n8k16.row.col.f32.f16.f16.f32 "
                    "{%0,%1,%2,%3}, {%4,%5,%6,%7}, {%8,%9}, {%0,%1,%2,%3};"
                    : "+f"(d0), "+f"(d1f), "+f"(d2f), "+f"(d3)
                    : "r"(A[kt][0]), "r"(A[kt][1]), "r"(A[kt][2]), "r"(A[kt][3]),
                      "r"(b0), "r"(b1r));
            }
            int col = nt * 8 + qi * 2;
            float bc0 = bb[col], bc1 = bb[col + 1];
            pm1 = fmaf(__sinf(d0 + bc0), t1r[2 * nt], pm1);
            pm1 = fmaf(__sinf(d1f + bc1), t1r[2 * nt + 1], pm1);
            pm2 = fmaf(__sinf(d2f + bc0), t2r[2 * nt], pm2);
            pm2 = fmaf(__sinf(d3 + bc1), t2r[2 * nt + 1], pm2);
        }
        pm1 += __shfl_xor_sync(0xffffffffu, pm1, 1);
        pm1 += __shfl_xor_sync(0xffffffffu, pm1, 2);
        pm2 += __shfl_xor_sync(0xffffffffu, pm2, 1);
        pm2 += __shfl_xor_sync(0xffffffffu, pm2, 2);
        if (qi == 0) {
            int c = cbase + cc;
            atomicAdd(&out[dA * 64 + c], pm1 + xbv1);
            atomicAdd(&out[dB * 64 + c], pm2 + xbv2);
        }
        // store prefetched B into the other buffer
        if (cc + 1 < CH) {
#pragma unroll
            for (int j = 0; j < 4; j++) {
                int i = j * 256 + tid, row = i >> 4, ch = i & 15;
                *(float4*)&Bnext[row * LDA + ch * 8] = pf[j];
            }
        }
        __syncthreads();
    }
}

// ---------------- post conv0 / pooling / build / decode ----------------
__global__ void k_post0() {
    int i = blockIdx.x * 256 + threadIdx.x;
    float v = sinf(0.01f * g_out0[i]);
    g_h0s[i] = v;
    g_maxkey[i] = fkey(v);
}
__global__ void k_smax(const int* __restrict__ ei, int E) {
    int idx = blockIdx.x * 256 + threadIdx.x;
    if (idx >= E * HH) return;
    int e = idx >> 6, c = idx & 63;
    int src = ei[e], dst = ei[E + e];
    atomicMax(&g_maxkey[dst * HH + c], fkey(g_h0s[src * HH + c]));
}
__global__ void k_build1(const int* __restrict__ keep, const float* __restrict__ ppos,
                         const float* __restrict__ bias1) {
    int i = blockIdx.x, t = threadIdx.x;
    int n = keep[i];
    g_xf1[i * FPAD + t] = funkey(g_maxkey[n * HH + t]);
    if (t < 3)  g_xf1[i * FPAD + 64 + t] = ppos[i * 3 + t];
    if (t == 3) g_xf1[i * FPAD + 67] = 0.f;
    g_out1[i * HH + t] = bias1[t];
}
__global__ void k_decode(const float* __restrict__ w, const float* __restrict__ b,
                         float* __restrict__ out) {
    __shared__ float hs[HH];
    int i = blockIdx.x, t = threadIdx.x;
    hs[t] = sinf(0.01f * g_out1[i * HH + t]);
    __syncthreads();
    if (t < LLAT) {
        float acc = b[t];
#pragma unroll
        for (int c = 0; c < HH; c++) acc = fmaf(hs[c], w[c * LLAT + t], acc);
        out[i * LLAT + t] = sinf(0.01f * acc);
    }
}

extern "C" void kernel_launch(void* const* d_in, const int* in_sizes, int n_in,
                              void* d_out, int out_size) {
    const float* x = (const float*)d_in[0];
    const float* pos;
    const int*   ei;
    int szEi;
    if (in_sizes[1] == NN0 * 3) { pos = (const float*)d_in[1]; ei = (const int*)d_in[2]; szEi = in_sizes[2]; }
    else                        { ei = (const int*)d_in[1]; pos = (const float*)d_in[2]; szEi = in_sizes[1]; }
    const int*   ei1    = (const int*)d_in[3];
    const float* ppos   = (const float*)d_in[4];
    const int*   keep   = (const int*)d_in[5];
    const float* lin0_w = (const float*)d_in[6];
    const float* lin0_b = (const float*)d_in[7];
    const float* lin1_w = (const float*)d_in[8];
    const float* lin1_b = (const float*)d_in[9];
    const float* c0w0 = (const float*)d_in[10], *c0b0 = (const float*)d_in[11];
    const float* c0w1 = (const float*)d_in[12], *c0b1 = (const float*)d_in[13];
    const float* c0w2 = (const float*)d_in[14], *c0b2 = (const float*)d_in[15];
    const float* c0bias = (const float*)d_in[16];
    const float* c1w0 = (const float*)d_in[17], *c1b0 = (const float*)d_in[18];
    const float* c1w1 = (const float*)d_in[19], *c1b1 = (const float*)d_in[20];
    const float* c1w2 = (const float*)d_in[21], *c1b2 = (const float*)d_in[22];
    const float* c1bias = (const float*)d_in[23];

    int E0 = szEi / 2, E1 = in_sizes[3] / 2;
    int E0t = E0 + NN0, E1t = E1 + NN1;     // 20480, 9216 (divisible by 128)
    int T0 = E0t / TM, T1 = E1t / TM;       // 160, 72

    float *xf0, *out0, *xf1, *out1, *tg, *xb2g;
    float4 *aim, *wcs;
    int *dstg;
    cudaGetSymbolAddress((void**)&xf0,  g_xf0);
    cudaGetSymbolAddress((void**)&out0, g_out0);
    cudaGetSymbolAddress((void**)&xf1,  g_xf1);
    cudaGetSymbolAddress((void**)&out1, g_out1);
    cudaGetSymbolAddress((void**)&aim,  g_aimg);
    cudaGetSymbolAddress((void**)&wcs,  g_w1cs);
    cudaGetSymbolAddress((void**)&tg,   g_t);
    cudaGetSymbolAddress((void**)&xb2g, g_xb2);
    cudaGetSymbolAddress((void**)&dstg, g_dst);

    cudaFuncSetAttribute(k_mma, cudaFuncAttributeMaxDynamicSharedMemorySize, SM_TOTAL);

    k_encode<<<NN0, 64>>>(x, pos, lin0_w, lin0_b, c0bias);
    k_prep<<<(E0t + 7) / 8, 256>>>(xf0, ei, E0, E0t, pos, c0w0, c0b0, c0w2, c0b2);
    k_w1cs<<<64, 64>>>(c0w0, c0w1);
    k_mma<<<T0 * CSPL, 256, SM_TOTAL>>>(aim, wcs, tg, xb2g, dstg, c0b1, out0);
    k_post0<<<(NN0 * HH) / 256, 256>>>();
    k_smax<<<(E0 * HH + 255) / 256, 256>>>(ei, E0);
    k_build1<<<NN1, 64>>>(keep, ppos, c1bias);
    k_prep<<<(E1t + 7) / 8, 256>>>(xf1, ei1, E1, E1t, ppos, c1w0, c1b0, c1w2, c1b2);
    k_w1cs<<<64, 64>>>(c1w0, c1w1);
    k_mma<<<T1 * CSPL, 256, SM_TOTAL>>>(aim, wcs, tg, xb2g, dstg, c1b1, out1);
    k_decode<<<NN1, 64>>>(lin1_w, lin1_b, (float*)d_out);
}

// round 13
// speedup vs baseline: 2.9149x; 1.1017x over previous
#include <cuda_runtime.h>
#include <cuda_fp16.h>
#include <math.h>
#include <stdint.h>

#define NN0 4096
#define NN1 1024
#define FIN 8
#define HH 64
#define FF 67
#define FPAD 68
#define LLAT 32
#define TM 128
#define CSPL 4          // channel splits per tile (16 channels per block)
#define MAXT 160        // max edge tiles (conv0: 20480/128)

// ---------------- device scratch (no allocation allowed) ----------------
__device__ float    g_xf0[NN0 * FPAD];
__device__ float    g_out0[NN0 * HH];
__device__ float    g_h0s[NN0 * HH];
__device__ unsigned g_maxkey[NN0 * HH];
__device__ float    g_xf1[NN1 * FPAD];
__device__ float    g_out1[NN1 * HH];
__device__ float4   g_aimg[MAXT * 2048];   // per tile: 128x128 f16 plain row-major (32KB)
__device__ float4   g_w1cs[64 * 1024];     // per c: 64x128 f16 plain row-major (16KB)
__device__ float    g_t[MAXT * 128 * 64];
__device__ float    g_xb2[MAXT * 128];
__device__ int      g_dst[MAXT * 128];

__device__ __forceinline__ unsigned fkey(float f) {
    int i = __float_as_int(f);
    return (i < 0) ? ~(unsigned)i : ((unsigned)i | 0x80000000u);
}
__device__ __forceinline__ float funkey(unsigned u) {
    int i = (u & 0x80000000u) ? (int)(u & 0x7fffffffu) : ~(int)u;
    return __int_as_float(i);
}
__device__ __forceinline__ uint32_t smem_u32(const void* p) {
    uint32_t a;
    asm("{ .reg .u64 t; cvta.to.shared.u64 t, %1; cvt.u32.u64 %0, t; }" : "=r"(a) : "l"(p));
    return a;
}
__device__ __forceinline__ void cp_async16(uint32_t dst, const void* src) {
    asm volatile("cp.async.cg.shared.global [%0], [%1], 16;" :: "r"(dst), "l"(src) : "memory");
}
__device__ __forceinline__ void cp_commit() {
    asm volatile("cp.async.commit_group;" ::: "memory");
}
__device__ __forceinline__ void cp_wait0() {
    asm volatile("cp.async.wait_group 0;" ::: "memory");
}

// ---------------- encode ----------------
__global__ void k_encode(const float* __restrict__ x, const float* __restrict__ pos,
                         const float* __restrict__ w, const float* __restrict__ b,
                         const float* __restrict__ bias0) {
    int n = blockIdx.x, t = threadIdx.x;  // block 64
    float acc = b[t];
#pragma unroll
    for (int f = 0; f < FIN; f++) acc = fmaf(x[n * FIN + f], w[f * HH + t], acc);
    g_xf0[n * FPAD + t] = sinf(0.01f * acc);
    if (t < 3)  g_xf0[n * FPAD + 64 + t] = pos[n * 3 + t];
    if (t == 3) g_xf0[n * FPAD + 67] = 0.f;
    g_out0[n * HH + t] = bias0[t];
}

// ---------------- prep: A image, t = x_j@w2^T, xb2, dst; tail blocks build B ----
__global__ __launch_bounds__(256)
void k_prep(const float* __restrict__ xf, const int* __restrict__ ei,
            int Eorig, int Etot, int PB, const float* __restrict__ pos,
            const float* __restrict__ w0, const float* __restrict__ b0,
            const float* __restrict__ w2, const float* __restrict__ b2,
            const float* __restrict__ w1) {
    int tid = threadIdx.x;
    if (blockIdx.x >= PB) {
        // ---- B image for channel c: rows n (64), cols k (128) f16, plain ----
        if (tid < 64) {
            int c = blockIdx.x - PB, n = tid;
            __half* img = (__half*)g_w1cs + c * 8192;
            float cf = (float)c;
#pragma unroll 8
            for (int j = 0; j < 32; j++) {
                int h0i = 2 * j, h1i = 2 * j + 1;
                float d0 = 0.1f * w0[192 + h0i], d1 = 0.1f * w0[192 + h1i];
                float w00 = w1[h0i * 64 + n],    w10 = w1[h1i * 64 + n];
                *(__half2*)&img[n * 128 + 2 * j] =
                    __floats2half2_rn(0.1f * __cosf(cf * d0) * w00, 0.1f * __cosf(cf * d1) * w10);
                *(__half2*)&img[n * 128 + 64 + 2 * j] =
                    __floats2half2_rn(0.1f * __sinf(cf * d0) * w00, 0.1f * __sinf(cf * d1) * w10);
            }
        }
        return;
    }

    __shared__ float w2s[HH * FF];
    __shared__ float w0s[192], b0s[HH], b2s[FF];
    __shared__ float xjs[8][FPAD];
    for (int i = tid; i < HH * FF; i += 256) w2s[i] = w2[i];
    if (tid < 192) w0s[tid] = 0.1f * w0[tid];
    if (tid < HH)  b0s[tid] = 0.1f * b0[tid];
    if (tid < FF)  b2s[tid] = b2[tid];
    __syncthreads();

    int w = tid >> 5, lane = tid & 31;
    int e = blockIdx.x * 8 + w;
    if (e >= Etot) return;
    int src, dst;
    if (e < Eorig) { src = ei[e]; dst = ei[Eorig + e]; }
    else           { src = dst = e - Eorig; }
    if (lane == 0) g_dst[e] = dst;

    float rx = pos[dst * 3 + 0] - pos[src * 3 + 0];
    float ry = pos[dst * 3 + 1] - pos[src * 3 + 1];
    float rz = pos[dst * 3 + 2] - pos[src * 3 + 2];
    float f0 = 0.f, f1 = 0.f, f2 = 0.f;
    if (!(rx == 0.f && ry == 0.f && rz == 0.f)) {
        float rho = sqrtf(rx * rx + ry * ry + rz * rz);
        const float INV_PI = 0.31830988618379067f;
        f0 = rho;
        f1 = atan2f(ry, rx) * INV_PI;
        f2 = asinf(fminf(fmaxf(rz / rho, -1.f), 1.f)) * INV_PI;
    }
    xjs[w][lane]      = xf[src * FPAD + lane];
    xjs[w][lane + 32] = xf[src * FPAD + lane + 32];
    if (lane < 4) xjs[w][lane + 64] = xf[src * FPAD + 64 + lane];
    __syncwarp();

    int ha = lane, hb = lane + 32;
    float t0 = 0.f, t1 = 0.f, xb2 = 0.f;
#pragma unroll
    for (int f = 0; f < FF; f++) {
        float xv = xjs[w][f];
        t0  = fmaf(w2s[ha * FF + f], xv, t0);
        t1  = fmaf(w2s[hb * FF + f], xv, t1);
        xb2 = fmaf(b2s[f], xv, xb2);
    }
    g_t[e * 64 + ha] = t0;
    g_t[e * 64 + hb] = t1;
    if (lane == 0) g_xb2[e] = xb2;

    // alpha for h = 2*lane, 2*lane+1 (pre-scaled by 0.1)
    int h0i = 2 * lane, h1i = 2 * lane + 1;
    float aA = fmaf(f0, w0s[h0i], fmaf(f1, w0s[64 + h0i], fmaf(f2, w0s[128 + h0i], b0s[h0i])));
    float aB = fmaf(f0, w0s[h1i], fmaf(f1, w0s[64 + h1i], fmaf(f2, w0s[128 + h1i], b0s[h1i])));
    // A row: cols [0,64) = sin(alpha_h), cols [64,128) = cos(alpha_h)
    __half* img = (__half*)g_aimg + (e >> 7) * 16384;
    int m = e & 127;
    *(__half2*)&img[m * 128 + 2 * lane]      = __floats2half2_rn(__sinf(aA), __sinf(aB));
    *(__half2*)&img[m * 128 + 64 + 2 * lane] = __floats2half2_rn(__cosf(aA), __cosf(aB));
}

// ---------------- HMMA kernel: block = (tile, 16-channel slice), 8 warps -------
// LDA=136 halves (272B stride; 272 mod 128 = 16 -> 8 ldmatrix rows sweep all banks)
#define LDA 136
#define SMA_BYTES   (128 * LDA * 2)              // 34816
#define SMB_BYTES   (64 * LDA * 2)               // 17408
#define SMB_OFF     SMA_BYTES
#define SMBB_OFF    (SMA_BYTES + 2 * SMB_BYTES)  // 69632
#define SM_TOTAL    (SMBB_OFF + 256)

__global__ __launch_bounds__(256, 2)
void k_mma(const float4* __restrict__ aimg, const float4* __restrict__ w1cs,
           const float* __restrict__ tg, const float* __restrict__ xb2g,
           const int* __restrict__ dstg, const float* __restrict__ b1,
           float* __restrict__ out) {
    extern __shared__ __align__(16) char sm[];
    __half* smA  = (__half*)sm;
    __half* smB0 = (__half*)(sm + SMB_OFF);
    __half* smB1 = (__half*)(sm + SMB_OFF + SMB_BYTES);
    float*  bb   = (float*)(sm + SMBB_OFF);

    int tid = threadIdx.x, w = tid >> 5, lane = tid & 31;
    int tile  = blockIdx.x / CSPL;
    int cbase = (blockIdx.x % CSPL) * (64 / CSPL);

    // copy A (padded) + B for first channel
    const float4* ag = aimg + tile * 2048;
    for (int i = tid; i < 2048; i += 256) {
        int row = i >> 4, ch = i & 15;
        *(float4*)&smA[row * LDA + ch * 8] = ag[i];
    }
    {
        const float4* bg = w1cs + cbase * 1024;
        for (int i = tid; i < 1024; i += 256) {
            int row = i >> 4, ch = i & 15;
            *(float4*)&smB0[row * LDA + ch * 8] = bg[i];
        }
    }
    if (tid < 64) bb[tid] = 0.1f * b1[tid];
    __syncthreads();

    // persistent A fragments: warp w owns edge rows 16w..16w+15
    uint32_t A[8][4];
    {
        int arow = 16 * w + (lane & 15);
#pragma unroll
        for (int kt = 0; kt < 8; kt++) {
            uint32_t a = smem_u32(&smA[arow * LDA + kt * 16 + (lane >> 4) * 8]);
            asm volatile("ldmatrix.sync.aligned.m8n8.x4.shared.b16 {%0,%1,%2,%3}, [%4];"
                         : "=r"(A[kt][0]), "=r"(A[kt][1]), "=r"(A[kt][2]), "=r"(A[kt][3])
                         : "r"(a));
        }
    }

    // per-thread t values (cols fixed across channels)
    int q = lane >> 2, qi = lane & 3;
    int r1 = 16 * w + q, r2 = r1 + 8;
    int e1 = tile * 128 + r1, e2 = tile * 128 + r2;
    float t1r[16], t2r[16];
#pragma unroll
    for (int nt = 0; nt < 8; nt++) {
        int col = nt * 8 + qi * 2;
        float2 v1 = *(const float2*)&tg[e1 * 64 + col];
        float2 v2 = *(const float2*)&tg[e2 * 64 + col];
        t1r[2 * nt] = v1.x; t1r[2 * nt + 1] = v1.y;
        t2r[2 * nt] = v2.x; t2r[2 * nt + 1] = v2.y;
    }
    float xbv1 = xb2g[e1], xbv2 = xb2g[e2];
    int dA = dstg[e1], dB = dstg[e2];

    // B ldmatrix base offset (x4: two kt chunks at once)
    int boff = (lane & 7) * LDA + ((lane >> 3) & 3) * 8;

    const int CH = 64 / CSPL;
    for (int cc = 0; cc < CH; cc++) {
        __half* Bcur  = (cc & 1) ? smB1 : smB0;
        __half* Bnext = (cc & 1) ? smB0 : smB1;
        // prefetch next channel's B via cp.async (no register staging)
        if (cc + 1 < CH) {
            const float4* nb = w1cs + (cbase + cc + 1) * 1024;
#pragma unroll
            for (int j = 0; j < 4; j++) {
                int i = j * 256 + tid, row = i >> 4, ch = i & 15;
                cp_async16(smem_u32(&Bnext[row * LDA + ch * 8]), nb + i);
            }
        }
        cp_commit();

        float pm1 = 0.f, pm2 = 0.f;
#pragma unroll
        for (int nt = 0; nt < 8; nt++) {
            float d0 = 0.f, d1f = 0.f, d2f = 0.f, d3 = 0.f;     // even-kt chain
            float g0 = 0.f, g1f = 0.f, g2f = 0.f, g3 = 0.f;     // odd-kt chain
#pragma unroll
            for (int kt = 0; kt < 8; kt += 2) {
                uint32_t ba = smem_u32(&Bcur[nt * 8 * LDA + kt * 16 + boff]);
                uint32_t b0, b1r, b2, b3r;
                asm volatile("ldmatrix.sync.aligned.m8n8.x4.shared.b16 {%0,%1,%2,%3}, [%4];"
                             : "=r"(b0), "=r"(b1r), "=r"(b2), "=r"(b3r) : "r"(ba));
                asm volatile(
                    "mma.sync.aligned.m16n8k16.row.col.f32.f16.f16.f32 "
                    "{%0,%1,%2,%3}, {%4,%5,%6,%7}, {%8,%9}, {%0,%1,%2,%3};"
                    : "+f"(d0), "+f"(d1f), "+f"(d2f), "+f"(d3)
                    : "r"(A[kt][0]), "r"(A[kt][1]), "r"(A[kt][2]), "r"(A[kt][3]),
                      "r"(b0), "r"(b1r));
                asm volatile(
                    "mma.sync.aligned.m16n8k16.row.col.f32.f16.f16.f32 "
                    "{%0,%1,%2,%3}, {%4,%5,%6,%7}, {%8,%9}, {%0,%1,%2,%3};"
                    : "+f"(g0), "+f"(g1f), "+f"(g2f), "+f"(g3)
                    : "r"(A[kt + 1][0]), "r"(A[kt + 1][1]), "r"(A[kt + 1][2]), "r"(A[kt + 1][3]),
                      "r"(b2), "r"(b3r));
            }
            int col = nt * 8 + qi * 2;
            float bc0 = bb[col], bc1 = bb[col + 1];
            pm1 = fmaf(__sinf(d0 + g0 + bc0), t1r[2 * nt], pm1);
            pm1 = fmaf(__sinf(d1f + g1f + bc1), t1r[2 * nt + 1], pm1);
            pm2 = fmaf(__sinf(d2f + g2f + bc0), t2r[2 * nt], pm2);
            pm2 = fmaf(__sinf(d3 + g3 + bc1), t2r[2 * nt + 1], pm2);
        }
        pm1 += __shfl_xor_sync(0xffffffffu, pm1, 1);
        pm1 += __shfl_xor_sync(0xffffffffu, pm1, 2);
        pm2 += __shfl_xor_sync(0xffffffffu, pm2, 1);
        pm2 += __shfl_xor_sync(0xffffffffu, pm2, 2);
        if (qi == 0) {
            int c = cbase + cc;
            atomicAdd(&out[dA * 64 + c], pm1 + xbv1);
            atomicAdd(&out[dB * 64 + c], pm2 + xbv2);
        }
        cp_wait0();
        __syncthreads();
    }
}

// ---------------- post conv0 / pooling / build / decode ----------------
__global__ void k_post0() {
    int i = blockIdx.x * 256 + threadIdx.x;
    float v = sinf(0.01f * g_out0[i]);
    g_h0s[i] = v;
    g_maxkey[i] = fkey(v);
}
__global__ void k_smax(const int* __restrict__ ei, int E) {
    int idx = blockIdx.x * 256 + threadIdx.x;
    if (idx >= E * HH) return;
    int e = idx >> 6, c = idx & 63;
    int src = ei[e], dst = ei[E + e];
    atomicMax(&g_maxkey[dst * HH + c], fkey(g_h0s[src * HH + c]));
}
__global__ void k_build1(const int* __restrict__ keep, const float* __restrict__ ppos,
                         const float* __restrict__ bias1) {
    int i = blockIdx.x, t = threadIdx.x;
    int n = keep[i];
    g_xf1[i * FPAD + t] = funkey(g_maxkey[n * HH + t]);
    if (t < 3)  g_xf1[i * FPAD + 64 + t] = ppos[i * 3 + t];
    if (t == 3) g_xf1[i * FPAD + 67] = 0.f;
    g_out1[i * HH + t] = bias1[t];
}
__global__ void k_decode(const float* __restrict__ w, const float* __restrict__ b,
                         float* __restrict__ out) {
    __shared__ float hs[HH];
    int i = blockIdx.x, t = threadIdx.x;
    hs[t] = sinf(0.01f * g_out1[i * HH + t]);
    __syncthreads();
    if (t < LLAT) {
        float acc = b[t];
#pragma unroll
        for (int c = 0; c < HH; c++) acc = fmaf(hs[c], w[c * LLAT + t], acc);
        out[i * LLAT + t] = sinf(0.01f * acc);
    }
}

extern "C" void kernel_launch(void* const* d_in, const int* in_sizes, int n_in,
                              void* d_out, int out_size) {
    const float* x = (const float*)d_in[0];
    const float* pos;
    const int*   ei;
    int szEi;
    if (in_sizes[1] == NN0 * 3) { pos = (const float*)d_in[1]; ei = (const int*)d_in[2]; szEi = in_sizes[2]; }
    else                        { ei = (const int*)d_in[1]; pos = (const float*)d_in[2]; szEi = in_sizes[1]; }
    const int*   ei1    = (const int*)d_in[3];
    const float* ppos   = (const float*)d_in[4];
    const int*   keep   = (const int*)d_in[5];
    const float* lin0_w = (const float*)d_in[6];
    const float* lin0_b = (const float*)d_in[7];
    const float* lin1_w = (const float*)d_in[8];
    const float* lin1_b = (const float*)d_in[9];
    const float* c0w0 = (const float*)d_in[10], *c0b0 = (const float*)d_in[11];
    const float* c0w1 = (const float*)d_in[12], *c0b1 = (const float*)d_in[13];
    const float* c0w2 = (const float*)d_in[14], *c0b2 = (const float*)d_in[15];
    const float* c0bias = (const float*)d_in[16];
    const float* c1w0 = (const float*)d_in[17], *c1b0 = (const float*)d_in[18];
    const float* c1w1 = (const float*)d_in[19], *c1b1 = (const float*)d_in[20];
    const float* c1w2 = (const float*)d_in[21], *c1b2 = (const float*)d_in[22];
    const float* c1bias = (const float*)d_in[23];

    int E0 = szEi / 2, E1 = in_sizes[3] / 2;
    int E0t = E0 + NN0, E1t = E1 + NN1;     // 20480, 9216 (divisible by 128)
    int T0 = E0t / TM, T1 = E1t / TM;       // 160, 72
    int PB0 = (E0t + 7) / 8, PB1 = (E1t + 7) / 8;

    float *xf0, *out0, *xf1, *out1, *tg, *xb2g;
    float4 *aim, *wcs;
    int *dstg;
    cudaGetSymbolAddress((void**)&xf0,  g_xf0);
    cudaGetSymbolAddress((void**)&out0, g_out0);
    cudaGetSymbolAddress((void**)&xf1,  g_xf1);
    cudaGetSymbolAddress((void**)&out1, g_out1);
    cudaGetSymbolAddress((void**)&aim,  g_aimg);
    cudaGetSymbolAddress((void**)&wcs,  g_w1cs);
    cudaGetSymbolAddress((void**)&tg,   g_t);
    cudaGetSymbolAddress((void**)&xb2g, g_xb2);
    cudaGetSymbolAddress((void**)&dstg, g_dst);

    cudaFuncSetAttribute(k_mma, cudaFuncAttributeMaxDynamicSharedMemorySize, SM_TOTAL);

    k_encode<<<NN0, 64>>>(x, pos, lin0_w, lin0_b, c0bias);
    k_prep<<<PB0 + 64, 256>>>(xf0, ei, E0, E0t, PB0, pos, c0w0, c0b0, c0w2, c0b2, c0w1);
    k_mma<<<T0 * CSPL, 256, SM_TOTAL>>>(aim, wcs, tg, xb2g, dstg, c0b1, out0);
    k_post0<<<(NN0 * HH) / 256, 256>>>();
    k_smax<<<(E0 * HH + 255) / 256, 256>>>(ei, E0);
    k_build1<<<NN1, 64>>>(keep, ppos, c1bias);
    k_prep<<<PB1 + 64, 256>>>(xf1, ei1, E1, E1t, PB1, ppos, c1w0, c1b0, c1w2, c1b2, c1w1);
    k_mma<<<T1 * CSPL, 256, SM_TOTAL>>>(aim, wcs, tg, xb2g, dstg, c1b1, out1);
    k_decode<<<NN1, 64>>>(lin1_w, lin1_b, (float*)d_out);
}

// round 16
// speedup vs baseline: 2.9501x; 1.0121x over previous
#include <cuda_runtime.h>
#include <cuda_fp16.h>
#include <math.h>
#include <stdint.h>

#define NN0 4096
#define NN1 1024
#define FIN 8
#define HH 64
#define FF 67
#define FPAD 68
#define LLAT 32
#define TM 128
#define MAXT 160        // max edge tiles (conv0: 20480/128)

// ---------------- device scratch (no allocation allowed) ----------------
__device__ float    g_xf0[NN0 * FPAD];
__device__ float    g_out0[NN0 * HH];
__device__ float    g_h0s[NN0 * HH];
__device__ unsigned g_maxkey[NN0 * HH];
__device__ float    g_xf1[NN1 * FPAD];
__device__ float    g_out1[NN1 * HH];
__device__ float4   g_aimg[MAXT * 2048];   // per tile: 128x128 f16 plain row-major (32KB)
__device__ float4   g_w1cs[64 * 1024];     // per c: 64x128 f16 plain row-major (16KB)
__device__ float    g_t[MAXT * 128 * 64];
__device__ float    g_xb2[MAXT * 128];
__device__ int      g_dst[MAXT * 128];

__device__ __forceinline__ unsigned fkey(float f) {
    int i = __float_as_int(f);
    return (i < 0) ? ~(unsigned)i : ((unsigned)i | 0x80000000u);
}
__device__ __forceinline__ float funkey(unsigned u) {
    int i = (u & 0x80000000u) ? (int)(u & 0x7fffffffu) : ~(int)u;
    return __int_as_float(i);
}
__device__ __forceinline__ uint32_t smem_u32(const void* p) {
    uint32_t a;
    asm("{ .reg .u64 t; cvta.to.shared.u64 t, %1; cvt.u32.u64 %0, t; }" : "=r"(a) : "l"(p));
    return a;
}
__device__ __forceinline__ void cp_async16(uint32_t dst, const void* src) {
    asm volatile("cp.async.cg.shared.global [%0], [%1], 16;" :: "r"(dst), "l"(src) : "memory");
}
__device__ __forceinline__ void cp_commit() {
    asm volatile("cp.async.commit_group;" ::: "memory");
}
__device__ __forceinline__ void cp_wait0() {
    asm volatile("cp.async.wait_group 0;" ::: "memory");
}

// ---------------- encode ----------------
__global__ void k_encode(const float* __restrict__ x, const float* __restrict__ pos,
                         const float* __restrict__ w, const float* __restrict__ b,
                         const float* __restrict__ bias0) {
    int n = blockIdx.x, t = threadIdx.x;  // block 64
    float acc = b[t];
#pragma unroll
    for (int f = 0; f < FIN; f++) acc = fmaf(x[n * FIN + f], w[f * HH + t], acc);
    g_xf0[n * FPAD + t] = sinf(0.01f * acc);
    if (t < 3)  g_xf0[n * FPAD + 64 + t] = pos[n * 3 + t];
    if (t == 3) g_xf0[n * FPAD + 67] = 0.f;
    g_out0[n * HH + t] = bias0[t];
}

// ---------------- prep: A image, t = x_j@w2^T, xb2, dst; tail blocks build B ----
__global__ __launch_bounds__(256)
void k_prep(const float* __restrict__ xf, const int* __restrict__ ei,
            int Eorig, int Etot, int PB, const float* __restrict__ pos,
            const float* __restrict__ w0, const float* __restrict__ b0,
            const float* __restrict__ w2, const float* __restrict__ b2,
            const float* __restrict__ w1) {
    int tid = threadIdx.x;
    if (blockIdx.x >= PB) {
        // ---- B image for channel c: rows n (64), cols k (128) f16, plain ----
        if (tid < 64) {
            int c = blockIdx.x - PB, n = tid;
            __half* img = (__half*)g_w1cs + c * 8192;
            float cf = (float)c;
#pragma unroll 8
            for (int j = 0; j < 32; j++) {
                int h0i = 2 * j, h1i = 2 * j + 1;
                float d0 = 0.1f * w0[192 + h0i], d1 = 0.1f * w0[192 + h1i];
                float w00 = w1[h0i * 64 + n],    w10 = w1[h1i * 64 + n];
                *(__half2*)&img[n * 128 + 2 * j] =
                    __floats2half2_rn(0.1f * __cosf(cf * d0) * w00, 0.1f * __cosf(cf * d1) * w10);
                *(__half2*)&img[n * 128 + 64 + 2 * j] =
                    __floats2half2_rn(0.1f * __sinf(cf * d0) * w00, 0.1f * __sinf(cf * d1) * w10);
            }
        }
        return;
    }

    __shared__ float w2s[HH * FF];
    __shared__ float w0s[192], b0s[HH], b2s[FF];
    __shared__ float xjs[8][FPAD];
    for (int i = tid; i < HH * FF; i += 256) w2s[i] = w2[i];
    if (tid < 192) w0s[tid] = 0.1f * w0[tid];
    if (tid < HH)  b0s[tid] = 0.1f * b0[tid];
    if (tid < FF)  b2s[tid] = b2[tid];
    __syncthreads();

    int w = tid >> 5, lane = tid & 31;
    int e = blockIdx.x * 8 + w;
    if (e >= Etot) return;
    int src, dst;
    if (e < Eorig) { src = ei[e]; dst = ei[Eorig + e]; }
    else           { src = dst = e - Eorig; }
    if (lane == 0) g_dst[e] = dst;

    float rx = pos[dst * 3 + 0] - pos[src * 3 + 0];
    float ry = pos[dst * 3 + 1] - pos[src * 3 + 1];
    float rz = pos[dst * 3 + 2] - pos[src * 3 + 2];
    float f0 = 0.f, f1 = 0.f, f2 = 0.f;
    if (!(rx == 0.f && ry == 0.f && rz == 0.f)) {
        float rho = sqrtf(rx * rx + ry * ry + rz * rz);
        const float INV_PI = 0.31830988618379067f;
        f0 = rho;
        f1 = atan2f(ry, rx) * INV_PI;
        f2 = asinf(fminf(fmaxf(rz / rho, -1.f), 1.f)) * INV_PI;
    }
    xjs[w][lane]      = xf[src * FPAD + lane];
    xjs[w][lane + 32] = xf[src * FPAD + lane + 32];
    if (lane < 4) xjs[w][lane + 64] = xf[src * FPAD + 64 + lane];
    __syncwarp();

    int ha = lane, hb = lane + 32;
    float t0 = 0.f, t1 = 0.f, xb2 = 0.f;
#pragma unroll
    for (int f = 0; f < FF; f++) {
        float xv = xjs[w][f];
        t0  = fmaf(w2s[ha * FF + f], xv, t0);
        t1  = fmaf(w2s[hb * FF + f], xv, t1);
        xb2 = fmaf(b2s[f], xv, xb2);
    }
    g_t[e * 64 + ha] = t0;
    g_t[e * 64 + hb] = t1;
    if (lane == 0) g_xb2[e] = xb2;

    // alpha for h = 2*lane, 2*lane+1 (pre-scaled by 0.1)
    int h0i = 2 * lane, h1i = 2 * lane + 1;
    float aA = fmaf(f0, w0s[h0i], fmaf(f1, w0s[64 + h0i], fmaf(f2, w0s[128 + h0i], b0s[h0i])));
    float aB = fmaf(f0, w0s[h1i], fmaf(f1, w0s[64 + h1i], fmaf(f2, w0s[128 + h1i], b0s[h1i])));
    // A row: cols [0,64) = sin(alpha_h), cols [64,128) = cos(alpha_h)
    __half* img = (__half*)g_aimg + (e >> 7) * 16384;
    int m = e & 127;
    *(__half2*)&img[m * 128 + 2 * lane]      = __floats2half2_rn(__sinf(aA), __sinf(aB));
    *(__half2*)&img[m * 128 + 64 + 2 * lane] = __floats2half2_rn(__cosf(aA), __cosf(aB));
}

// ---------------- HMMA kernel: block = (tile, CH-channel slice), 8 warps -------
// LDA=136 halves (272B stride; 272 mod 128 = 16 -> 8 ldmatrix rows sweep all banks)
#define LDA 136
#define SMA_BYTES   (128 * LDA * 2)              // 34816
#define SMB_BYTES   (64 * LDA * 2)               // 17408
#define SMB_OFF     SMA_BYTES
#define SMBB_OFF    (SMA_BYTES + 2 * SMB_BYTES)  // 69632
#define SM_TOTAL    (SMBB_OFF + 256)

template <int CH>
__global__ __launch_bounds__(256, 2)
void k_mma(const float4* __restrict__ aimg, const float4* __restrict__ w1cs,
           const float* __restrict__ tg, const float* __restrict__ xb2g,
           const int* __restrict__ dstg, const float* __restrict__ b1,
           float* __restrict__ out) {
    extern __shared__ __align__(16) char sm[];
    __half* smA  = (__half*)sm;
    __half* smB0 = (__half*)(sm + SMB_OFF);
    __half* smB1 = (__half*)(sm + SMB_OFF + SMB_BYTES);
    float*  bb   = (float*)(sm + SMBB_OFF);

    const int CSPL = 64 / CH;
    int tid = threadIdx.x, w = tid >> 5, lane = tid & 31;
    int tile  = blockIdx.x / CSPL;
    int cbase = (blockIdx.x % CSPL) * CH;

    // copy A (padded) + B for first channel
    const float4* ag = aimg + tile * 2048;
    for (int i = tid; i < 2048; i += 256) {
        int row = i >> 4, ch = i & 15;
        *(float4*)&smA[row * LDA + ch * 8] = ag[i];
    }
    {
        const float4* bg = w1cs + cbase * 1024;
        for (int i = tid; i < 1024; i += 256) {
            int row = i >> 4, ch = i & 15;
            *(float4*)&smB0[row * LDA + ch * 8] = bg[i];
        }
    }
    if (tid < 64) bb[tid] = 0.1f * b1[tid];
    __syncthreads();

    // persistent A fragments: warp w owns edge rows 16w..16w+15
    uint32_t A[8][4];
    {
        int arow = 16 * w + (lane & 15);
#pragma unroll
        for (int kt = 0; kt < 8; kt++) {
            uint32_t a = smem_u32(&smA[arow * LDA + kt * 16 + (lane >> 4) * 8]);
            asm volatile("ldmatrix.sync.aligned.m8n8.x4.shared.b16 {%0,%1,%2,%3}, [%4];"
                         : "=r"(A[kt][0]), "=r"(A[kt][1]), "=r"(A[kt][2]), "=r"(A[kt][3])
                         : "r"(a));
        }
    }

    // per-thread t values (cols fixed across channels)
    int q = lane >> 2, qi = lane & 3;
    int r1 = 16 * w + q, r2 = r1 + 8;
    int e1 = tile * 128 + r1, e2 = tile * 128 + r2;
    float t1r[16], t2r[16];
#pragma unroll
    for (int nt = 0; nt < 8; nt++) {
        int col = nt * 8 + qi * 2;
        float2 v1 = *(const float2*)&tg[e1 * 64 + col];
        float2 v2 = *(const float2*)&tg[e2 * 64 + col];
        t1r[2 * nt] = v1.x; t1r[2 * nt + 1] = v1.y;
        t2r[2 * nt] = v2.x; t2r[2 * nt + 1] = v2.y;
    }
    float xbv1 = xb2g[e1], xbv2 = xb2g[e2];
    int dA = dstg[e1], dB = dstg[e2];

    // B ldmatrix base offset (x4: two kt chunks at once)
    int boff = (lane & 7) * LDA + ((lane >> 3) & 3) * 8;

    for (int cc = 0; cc < CH; cc++) {
        __half* Bcur  = (cc & 1) ? smB1 : smB0;
        __half* Bnext = (cc & 1) ? smB0 : smB1;
        // prefetch next channel's B via cp.async (no register staging)
        if (cc + 1 < CH) {
            const float4* nb = w1cs + (cbase + cc + 1) * 1024;
#pragma unroll
            for (int j = 0; j < 4; j++) {
                int i = j * 256 + tid, row = i >> 4, ch = i & 15;
                cp_async16(smem_u32(&Bnext[row * LDA + ch * 8]), nb + i);
            }
            cp_commit();
        }

        float pm1 = 0.f, pm2 = 0.f;
#pragma unroll
        for (int nt = 0; nt < 8; nt++) {
            float d0 = 0.f, d1f = 0.f, d2f = 0.f, d3 = 0.f;     // even-kt chain
            float g0 = 0.f, g1f = 0.f, g2f = 0.f, g3 = 0.f;     // odd-kt chain
#pragma unroll
            for (int kt = 0; kt < 8; kt += 2) {
                uint32_t ba = smem_u32(&Bcur[nt * 8 * LDA + kt * 16 + boff]);
                uint32_t b0, b1r, b2, b3r;
                asm volatile("ldmatrix.sync.aligned.m8n8.x4.shared.b16 {%0,%1,%2,%3}, [%4];"
                             : "=r"(b0), "=r"(b1r), "=r"(b2), "=r"(b3r) : "r"(ba));
                asm volatile(
                    "mma.sync.aligned.m16n8k16.row.col.f32.f16.f16.f32 "
                    "{%0,%1,%2,%3}, {%4,%5,%6,%7}, {%8,%9}, {%0,%1,%2,%3};"
                    : "+f"(d0), "+f"(d1f), "+f"(d2f), "+f"(d3)
                    : "r"(A[kt][0]), "r"(A[kt][1]), "r"(A[kt][2]), "r"(A[kt][3]),
                      "r"(b0), "r"(b1r));
                asm volatile(
                    "mma.sync.aligned.m16n8k16.row.col.f32.f16.f16.f32 "
                    "{%0,%1,%2,%3}, {%4,%5,%6,%7}, {%8,%9}, {%0,%1,%2,%3};"
                    : "+f"(g0), "+f"(g1f), "+f"(g2f), "+f"(g3)
                    : "r"(A[kt + 1][0]), "r"(A[kt + 1][1]), "r"(A[kt + 1][2]), "r"(A[kt + 1][3]),
                      "r"(b2), "r"(b3r));
            }
            int col = nt * 8 + qi * 2;
            float bc0 = bb[col], bc1 = bb[col + 1];
            pm1 = fmaf(__sinf(d0 + g0 + bc0), t1r[2 * nt], pm1);
            pm1 = fmaf(__sinf(d1f + g1f + bc1), t1r[2 * nt + 1], pm1);
            pm2 = fmaf(__sinf(d2f + g2f + bc0), t2r[2 * nt], pm2);
            pm2 = fmaf(__sinf(d3 + g3 + bc1), t2r[2 * nt + 1], pm2);
        }
        pm1 += __shfl_xor_sync(0xffffffffu, pm1, 1);
        pm1 += __shfl_xor_sync(0xffffffffu, pm1, 2);
        pm2 += __shfl_xor_sync(0xffffffffu, pm2, 1);
        pm2 += __shfl_xor_sync(0xffffffffu, pm2, 2);
        if (qi == 0) {
            int c = cbase + cc;
            atomicAdd(&out[dA * 64 + c], pm1 + xbv1);
            atomicAdd(&out[dB * 64 + c], pm2 + xbv2);
        }
        if (cc + 1 < CH) {
            cp_wait0();
            __syncthreads();
        }
    }
}

// ---------------- post conv0 / pooling / build / decode ----------------
__global__ void k_post0() {
    int i = blockIdx.x * 256 + threadIdx.x;
    float v = sinf(0.01f * g_out0[i]);
    g_h0s[i] = v;
    g_maxkey[i] = fkey(v);
}
__global__ void k_smax(const int* __restrict__ ei, int E) {
    int idx = blockIdx.x * 256 + threadIdx.x;
    if (idx >= E * HH) return;
    int e = idx >> 6, c = idx & 63;
    int src = ei[e], dst = ei[E + e];
    atomicMax(&g_maxkey[dst * HH + c], fkey(g_h0s[src * HH + c]));
}
__global__ void k_build1(const int* __restrict__ keep, const float* __restrict__ ppos,
                         const float* __restrict__ bias1) {
    int i = blockIdx.x, t = threadIdx.x;
    int n = keep[i];
    g_xf1[i * FPAD + t] = funkey(g_maxkey[n * HH + t]);
    if (t < 3)  g_xf1[i * FPAD + 64 + t] = ppos[i * 3 + t];
    if (t == 3) g_xf1[i * FPAD + 67] = 0.f;
    g_out1[i * HH + t] = bias1[t];
}
__global__ void k_decode(const float* __restrict__ w, const float* __restrict__ b,
                         float* __restrict__ out) {
    __shared__ float hs[HH];
    int i = blockIdx.x, t = threadIdx.x;
    hs[t] = sinf(0.01f * g_out1[i * HH + t]);
    __syncthreads();
    if (t < LLAT) {
        float acc = b[t];
#pragma unroll
        for (int c = 0; c < HH; c++) acc = fmaf(hs[c], w[c * LLAT + t], acc);
        out[i * LLAT + t] = sinf(0.01f * acc);
    }
}

extern "C" void kernel_launch(void* const* d_in, const int* in_sizes, int n_in,
                              void* d_out, int out_size) {
    const float* x = (const float*)d_in[0];
    const float* pos;
    const int*   ei;
    int szEi;
    if (in_sizes[1] == NN0 * 3) { pos = (const float*)d_in[1]; ei = (const int*)d_in[2]; szEi = in_sizes[2]; }
    else                        { ei = (const int*)d_in[1]; pos = (const float*)d_in[2]; szEi = in_sizes[1]; }
    const int*   ei1    = (const int*)d_in[3];
    const float* ppos   = (const float*)d_in[4];
    const int*   keep   = (const int*)d_in[5];
    const float* lin0_w = (const float*)d_in[6];
    const float* lin0_b = (const float*)d_in[7];
    const float* lin1_w = (const float*)d_in[8];
    const float* lin1_b = (const float*)d_in[9];
    const float* c0w0 = (const float*)d_in[10], *c0b0 = (const float*)d_in[11];
    const float* c0w1 = (const float*)d_in[12], *c0b1 = (const float*)d_in[13];
    const float* c0w2 = (const float*)d_in[14], *c0b2 = (const float*)d_in[15];
    const float* c0bias = (const float*)d_in[16];
    const float* c1w0 = (const float*)d_in[17], *c1b0 = (const float*)d_in[18];
    const float* c1w1 = (const float*)d_in[19], *c1b1 = (const float*)d_in[20];
    const float* c1w2 = (const float*)d_in[21], *c1b2 = (const float*)d_in[22];
    const float* c1bias = (const float*)d_in[23];

    int E0 = szEi / 2, E1 = in_sizes[3] / 2;
    int E0t = E0 + NN0, E1t = E1 + NN1;     // 20480, 9216 (divisible by 128)
    int T0 = E0t / TM, T1 = E1t / TM;       // 160, 72
    int PB0 = (E0t + 7) / 8, PB1 = (E1t + 7) / 8;

    float *xf0, *out0, *xf1, *out1, *tg, *xb2g;
    float4 *aim, *wcs;
    int *dstg;
    cudaGetSymbolAddress((void**)&xf0,  g_xf0);
    cudaGetSymbolAddress((void**)&out0, g_out0);
    cudaGetSymbolAddress((void**)&xf1,  g_xf1);
    cudaGetSymbolAddress((void**)&out1, g_out1);
    cudaGetSymbolAddress((void**)&aim,  g_aimg);
    cudaGetSymbolAddress((void**)&wcs,  g_w1cs);
    cudaGetSymbolAddress((void**)&tg,   g_t);
    cudaGetSymbolAddress((void**)&xb2g, g_xb2);
    cudaGetSymbolAddress((void**)&dstg, g_dst);

    cudaFuncSetAttribute(k_mma<8>,  cudaFuncAttributeMaxDynamicSharedMemorySize, SM_TOTAL);
    cudaFuncSetAttribute(k_mma<16>, cudaFuncAttributeMaxDynamicSharedMemorySize, SM_TOTAL);

    k_encode<<<NN0, 64>>>(x, pos, lin0_w, lin0_b, c0bias);
    k_prep<<<PB0 + 64, 256>>>(xf0, ei, E0, E0t, PB0, pos, c0w0, c0b0, c0w2, c0b2, c0w1);
    k_mma<8><<<T0 * 8, 256, SM_TOTAL>>>(aim, wcs, tg, xb2g, dstg, c0b1, out0);
    k_post0<<<(NN0 * HH) / 256, 256>>>();
    k_smax<<<(E0 * HH + 255) / 256, 256>>>(ei, E0);
    k_build1<<<NN1, 64>>>(keep, ppos, c1bias);
    k_prep<<<PB1 + 64, 256>>>(xf1, ei1, E1, E1t, PB1, ppos, c1w0, c1b0, c1w2, c1b2, c1w1);
    k_mma<16><<<T1 * 4, 256, SM_TOTAL>>>(aim, wcs, tg, xb2g, dstg, c1b1, out1);
    k_decode<<<NN1, 64>>>(lin1_w, lin1_b, (float*)d_out);
}